// round 14
// baseline (speedup 1.0000x reference)
#include <cuda_runtime.h>
#include <cuda_bf16.h>
#include <cuda_fp16.h>
#include <cstdint>
#include <math.h>

// Problem constants
#define Bq   8
#define Sq   1024
#define Dq   512
#define Hq   8
#define DHq  64
#define BSr  (Bq*Sq)        // 8192 rows
#define BSD  (Bq*Sq*Dq)     // 4194304 elements

#define LOG2E_DIV_H 0.18033688f    // log2(e)/8

// ---------------- device scratch (no allocations allowed) ----------------
__device__ float g_E [BSD];
__device__ float g_DI[BSD];
__device__ float g_S [BSD];
__device__ float g_I [BSD];
__device__ __half g_A16[BSD];
__device__ __half g_Q16[BSD];     // pre-scaled by LOG2E_DIV_H
__device__ __half g_K16[BSD];
__device__ __half g_V16[BSD];
__device__ __half g_EO16[BSD];    // enc_out fp16 (K/V role in eda)
__device__ __half g_EOq16[BSD];   // enc_out fp16 pre-scaled (Q role in eda)
__device__ __half g_W16[8 * Dq * Dq];   // transposed weights [n][k], fp16

// ---------------- helpers (non-'a' ISA only) ----------------
__device__ __forceinline__ uint32_t smem_u32(const void* p) {
    uint32_t a;
    asm("{ .reg .u64 t; cvta.to.shared.u64 t, %1; cvt.u32.u64 %0, t; }" : "=r"(a) : "l"(p));
    return a;
}
__device__ __forceinline__ void ldsm_x4(uint32_t* r, uint32_t addr) {
    asm volatile("ldmatrix.sync.aligned.m8n8.x4.shared.b16 {%0,%1,%2,%3}, [%4];"
        : "=r"(r[0]), "=r"(r[1]), "=r"(r[2]), "=r"(r[3]) : "r"(addr));
}
__device__ __forceinline__ void ldsm_x4t(uint32_t* r, uint32_t addr) {
    asm volatile("ldmatrix.sync.aligned.m8n8.x4.trans.shared.b16 {%0,%1,%2,%3}, [%4];"
        : "=r"(r[0]), "=r"(r[1]), "=r"(r[2]), "=r"(r[3]) : "r"(addr));
}
__device__ __forceinline__ void mma16816h(float* c, const uint32_t* a, const uint32_t* b) {
    asm volatile("mma.sync.aligned.m16n8k16.row.col.f32.f16.f16.f32 "
        "{%0,%1,%2,%3}, {%4,%5,%6,%7}, {%8,%9}, {%0,%1,%2,%3};"
        : "+f"(c[0]), "+f"(c[1]), "+f"(c[2]), "+f"(c[3])
        : "r"(a[0]), "r"(a[1]), "r"(a[2]), "r"(a[3]), "r"(b[0]), "r"(b[1]));
}
__device__ __forceinline__ uint32_t pkh2(float a, float b) {
    __half2 h = __floats2half2_rn(a, b);
    return *(uint32_t*)&h;
}
// exp2 of a packed (a-m, b-m) pair, result as fp16x2 fragment word + fp32 sum accumulation
__device__ __forceinline__ uint32_t pexp2(float a, float b, float m, float& sum) {
    __half2 h = h2exp2(__floats2half2_rn(a - m, b - m));
    float2 f = __half22float2(h);
    sum += f.x + f.y;
    return *(uint32_t*)&h;
}
#define CPA16(sa, gp) asm volatile("cp.async.cg.shared.global [%0], [%1], 16;" :: "r"(sa), "l"(gp))
#define CP_COMMIT()   asm volatile("cp.async.commit_group;")
#define CP_WAIT0()    asm volatile("cp.async.wait_group 0;" ::: "memory")

// ---------------- fused weight convert + transpose (all 8, fp16) ----------------
__global__ void __launch_bounds__(256) cvt_wt_all_kernel(
    const float* __restrict__ W0, const float* __restrict__ W1,
    const float* __restrict__ W2, const float* __restrict__ W3,
    const float* __restrict__ W4, const float* __restrict__ W5,
    const float* __restrict__ W6, const float* __restrict__ W7,
    __half* __restrict__ o16) {
    int w = blockIdx.y;
    const float* W = (w == 0) ? W0 : (w == 1) ? W1 : (w == 2) ? W2 : (w == 3) ? W3 :
                     (w == 4) ? W4 : (w == 5) ? W5 : (w == 6) ? W6 : W7;
    int idx = blockIdx.x * 256 + threadIdx.x;   // idx = n*512 + k
    int n = idx >> 9, k = idx & 511;
    o16[(size_t)w * Dq * Dq + idx] = __float2half_rn(W[k * Dq + n]);
}

// ---------------- positional-embedding add (fp32 + fp16 out) ----------------
__global__ void __launch_bounds__(256) add_pos_kernel(const float* __restrict__ x,
                                                      float* __restrict__ out,
                                                      __half* __restrict__ o16) {
    int idx = blockIdx.x * 256 + threadIdx.x;
    int d = idx & (Dq - 1);
    int s = (idx >> 9) & (Sq - 1);
    float freq  = expf((float)d * -0.0359778920794f);
    float angle = (float)s * freq;
    float pe = (d & 1) ? cosf(angle) : sinf(angle);
    float r = x[idx] + pe;
    out[idx] = r;
    o16[idx] = __float2half_rn(r);
}

// ---------------- fused LayerNorm + residual ----------------
__global__ void __launch_bounds__(256) ln_add_kernel(const float* __restrict__ x,
                                                     const float* __restrict__ gamma,
                                                     const float* __restrict__ beta,
                                                     const float* __restrict__ basep,
                                                     float scale,
                                                     float* __restrict__ out,
                                                     __half* __restrict__ o16) {
    __shared__ float red[256];
    int t = threadIdx.x;
    size_t off = (size_t)blockIdx.x * Dq;

    float v0 = x[off + t];
    float v1 = x[off + t + 256];

    red[t] = v0 + v1;
    __syncthreads();
    #pragma unroll
    for (int s2 = 128; s2 > 0; s2 >>= 1) {
        if (t < s2) red[t] += red[t + s2];
        __syncthreads();
    }
    float mu = red[0] * (1.0f / 512.0f);
    __syncthreads();

    float d0 = v0 - mu, d1 = v1 - mu;
    red[t] = d0 * d0 + d1 * d1;
    __syncthreads();
    #pragma unroll
    for (int s2 = 128; s2 > 0; s2 >>= 1) {
        if (t < s2) red[t] += red[t + s2];
        __syncthreads();
    }
    float var = red[0] * (1.0f / 512.0f);
    float rs  = rsqrtf(var + 1e-3f);

    float r0 = basep[off + t]       + scale * (d0 * rs * gamma[t]       + beta[t]);
    float r1 = basep[off + t + 256] + scale * (d1 * rs * gamma[t + 256] + beta[t + 256]);
    out[off + t]       = r0;
    out[off + t + 256] = r1;
    if (o16) {
        o16[off + t]       = __float2half_rn(r0);
        o16[off + t + 256] = __float2half_rn(r1);
    }
}

// ---------------- GEMM core: 128x128 tile, fp16 single pass ----------------
#define APAD 72
#define SA16 0
#define SB16 18432
#define GEMM_SMEM 36864

struct GemmFrag { float acc[2][8][4]; };

__device__ __forceinline__ void gemm_core(uint32_t sb, char* smem,
                                          const __half* __restrict__ A16,
                                          const __half* __restrict__ B16,
                                          int m0, int n0, GemmFrag& F) {
    __half* sA = (__half*)(smem + SA16);
    __half* sB = (__half*)(smem + SB16);

    int tid = threadIdx.x;
    int wid = tid >> 5, lane = tid & 31;
    int wm = (wid & 3) * 32;
    int wn = (wid >> 2) * 64;

    #pragma unroll
    for (int i = 0; i < 2; i++)
        #pragma unroll
        for (int j = 0; j < 8; j++)
            #pragma unroll
            for (int q = 0; q < 4; q++) F.acc[i][j][q] = 0.0f;

    int la = lane & 15;
    int lacol = (lane >> 4) << 3;
    int nrow = (lane & 7) + ((lane >> 4) << 3);
    int koff = ((lane >> 3) & 1) << 3;

    int rT = tid >> 1, cT = (tid & 1) * 32;

    for (int kc = 0; kc < 8; kc++) {
        int kofs = kc * 64;
        #pragma unroll
        for (int q = 0; q < 4; q++) {
            size_t goA = (size_t)(m0 + rT) * Dq + kofs + cT + q * 8;
            size_t goB = (size_t)(n0 + rT) * Dq + kofs + cT + q * 8;
            *(uint4*)&sA[rT * APAD + cT + q * 8] = *(const uint4*)&A16[goA];
            *(uint4*)&sB[rT * APAD + cT + q * 8] = *(const uint4*)&B16[goB];
        }
        __syncthreads();

        #pragma unroll
        for (int ks = 0; ks < 4; ks++) {
            int kk = ks * 16;
            uint32_t a[2][4];
            #pragma unroll
            for (int ma = 0; ma < 2; ma++) {
                int row = wm + ma * 16 + la;
                ldsm_x4(a[ma], sb + SA16 + (uint32_t)((row * APAD + kk + lacol) * 2));
            }
            uint32_t bq[4][4];
            #pragma unroll
            for (int nb = 0; nb < 4; nb++) {
                int rown = wn + nb * 16 + nrow;
                ldsm_x4(bq[nb], sb + SB16 + (uint32_t)((rown * APAD + kk + koff) * 2));
            }
            #pragma unroll
            for (int ma = 0; ma < 2; ma++)
                #pragma unroll
                for (int nb = 0; nb < 4; nb++) {
                    mma16816h(F.acc[ma][2 * nb],     a[ma], &bq[nb][0]);
                    mma16816h(F.acc[ma][2 * nb + 1], a[ma], &bq[nb][2]);
                }
        }
        __syncthreads();
    }
}

// ---- generic GEMM: fp32 out (+addend) and/or fp16 out (+scaled fp16 copy) ----
__global__ void __launch_bounds__(256) gemm_mma_kernel(
    const __half* __restrict__ A16, const __half* __restrict__ B16,
    const float* __restrict__ addend, float* __restrict__ C,
    __half* __restrict__ C16, __half* __restrict__ C16s) {
    extern __shared__ char smem[];
    uint32_t sb = smem_u32(smem);
    int m0 = blockIdx.y * 128, n0 = blockIdx.x * 128;
    GemmFrag F;
    gemm_core(sb, smem, A16, B16, m0, n0, F);

    int wid = threadIdx.x >> 5, lane = threadIdx.x & 31;
    int wm = (wid & 3) * 32, wn = (wid >> 2) * 64;
    int g = lane >> 2, tq = lane & 3;
    #pragma unroll
    for (int ma = 0; ma < 2; ma++) {
        int row = m0 + wm + ma * 16 + g;
        #pragma unroll
        for (int na = 0; na < 8; na++) {
            int col = n0 + wn + na * 8 + tq * 2;
            size_t o0 = (size_t)row * Dq + col;
            size_t o1 = o0 + 8 * Dq;
            float2 r0 = make_float2(F.acc[ma][na][0], F.acc[ma][na][1]);
            float2 r1 = make_float2(F.acc[ma][na][2], F.acc[ma][na][3]);
            if (addend) {
                float2 a0 = *(const float2*)&addend[o0];
                float2 a1 = *(const float2*)&addend[o1];
                r0.x += a0.x; r0.y += a0.y;
                r1.x += a1.x; r1.y += a1.y;
            }
            if (C) {
                *(float2*)&C[o0] = r0;
                *(float2*)&C[o1] = r1;
            }
            if (C16) {
                *(uint32_t*)&C16[o0] = pkh2(r0.x, r0.y);
                *(uint32_t*)&C16[o1] = pkh2(r1.x, r1.y);
            }
            if (C16s) {
                *(uint32_t*)&C16s[o0] = pkh2(r0.x * LOG2E_DIV_H, r0.y * LOG2E_DIV_H);
                *(uint32_t*)&C16s[o1] = pkh2(r1.x * LOG2E_DIV_H, r1.y * LOG2E_DIV_H);
            }
        }
    }
}

// ---- fused QKV GEMM: Q pre-scaled by LOG2E_DIV_H ----
__global__ void __launch_bounds__(256) gemm_qkv_kernel(
    const __half* __restrict__ A16, const __half* __restrict__ W16,
    __half* __restrict__ Q16, __half* __restrict__ K16, __half* __restrict__ V16) {
    extern __shared__ char smem[];
    uint32_t sb = smem_u32(smem);
    int w = blockIdx.x >> 2;                 // 0=Q,1=K,2=V
    int n0 = (blockIdx.x & 3) * 128;
    int m0 = blockIdx.y * 128;
    const __half* B16 = W16 + (size_t)w * Dq * Dq;
    __half* O16 = (w == 0) ? Q16 : (w == 1) ? K16 : V16;
    float sc = (w == 0) ? LOG2E_DIV_H : 1.0f;

    GemmFrag F;
    gemm_core(sb, smem, A16, B16, m0, n0, F);

    int wid = threadIdx.x >> 5, lane = threadIdx.x & 31;
    int wm = (wid & 3) * 32, wn = (wid >> 2) * 64;
    int g = lane >> 2, tq = lane & 3;
    #pragma unroll
    for (int ma = 0; ma < 2; ma++) {
        int row = m0 + wm + ma * 16 + g;
        #pragma unroll
        for (int na = 0; na < 8; na++) {
            int col = n0 + wn + na * 8 + tq * 2;
            size_t o0 = (size_t)row * Dq + col;
            size_t o1 = o0 + 8 * Dq;
            *(uint32_t*)&O16[o0] = pkh2(F.acc[ma][na][0] * sc, F.acc[ma][na][1] * sc);
            *(uint32_t*)&O16[o1] = pkh2(F.acc[ma][na][2] * sc, F.acc[ma][na][3] * sc);
        }
    }
}

// ---------------- flash attention: 128q, fp16, dbuf KV, paired LDSM, h2exp2 softmax ----------------
// Q arrives pre-scaled by LOG2E_DIV_H, so sacc is directly in exp2 domain.
#define FP 72
#define FQ16 0
#define FKV  18432
#define KK16 0
#define VV16 9216
#define KVBUF 18432
#define FLASH_SMEM (FKV + 2 * KVBUF)   // 55296 -> 2 CTAs/SM

__global__ void __launch_bounds__(256) flash_mma_kernel(
    const __half* __restrict__ Q16,
    const __half* __restrict__ K16,
    const __half* __restrict__ V16,
    float* __restrict__ O,
    __half* __restrict__ O16) {
    extern __shared__ char smem[];
    uint32_t sb = smem_u32(smem);

    int tid = threadIdx.x, wid = tid >> 5, lane = tid & 31;
    int wm = wid * 16;
    int g = lane >> 2, tq = lane & 3;
    int qb = blockIdx.x, h = blockIdx.y, b = blockIdx.z;
    size_t baseQ  = ((size_t)b * Sq + (size_t)qb * 128) * Dq + h * DHq;
    size_t baseKV = (size_t)b * Sq * Dq + h * DHq;

    int rQ = tid >> 1, cQ = (tid & 1) * 32;
    int rK = tid >> 2, cK = (tid & 3) * 16;

    auto kvload = [&](int kb, uint32_t bofs) {
        size_t go = baseKV + (size_t)(kb * 64 + rK) * Dq + cK;
        uint32_t so = sb + FKV + bofs + (uint32_t)((rK * FP + cK) * 2);
        #pragma unroll
        for (int q = 0; q < 2; q++) {
            CPA16(so + KK16 + q * 16, &K16[go + q * 8]);
            CPA16(so + VV16 + q * 16, &V16[go + q * 8]);
        }
    };

    {   // Q + KV tile 0
        size_t go = baseQ + (size_t)rQ * Dq + cQ;
        uint32_t so = sb + FQ16 + (uint32_t)((rQ * FP + cQ) * 2);
        #pragma unroll
        for (int q = 0; q < 4; q++)
            CPA16(so + q * 16, &Q16[go + q * 8]);
        kvload(0, 0);
        CP_COMMIT();
        CP_WAIT0();
        __syncthreads();
    }

    float oacc[8][4];
    #pragma unroll
    for (int j = 0; j < 8; j++)
        #pragma unroll
        for (int q = 0; q < 4; q++) oacc[j][q] = 0.0f;
    float mr0 = -1e30f, mr1 = -1e30f, lr0 = 0.0f, lr1 = 0.0f;

    uint32_t aQ = (uint32_t)(((wm + (lane & 15)) * FP + ((lane >> 4) << 3)) * 2);
    int nrow = (lane & 7) + ((lane >> 4) << 3);
    int koff = ((lane >> 3) & 1) << 3;
    uint32_t bKp = (uint32_t)((nrow * FP + koff) * 2);
    uint32_t bVp = (uint32_t)(((lane & 15) * FP + ((lane >> 4) << 3)) * 2);

    for (int kb = 0; kb < 16; kb++) {
        uint32_t cur = FKV + ((kb & 1) ? KVBUF : 0);
        if (kb < 15) {
            kvload(kb + 1, (kb & 1) ? 0 : KVBUF);
            CP_COMMIT();
        }

        // S = Q @ K^T (single-pass fp16, paired B fetch); already exp2-domain
        float sacc[8][4];
        #pragma unroll
        for (int j = 0; j < 8; j++)
            #pragma unroll
            for (int q = 0; q < 4; q++) sacc[j][q] = 0.0f;

        #pragma unroll
        for (int ks = 0; ks < 4; ks++) {
            uint32_t aq[4];
            ldsm_x4(aq, sb + FQ16 + aQ + ks * 32);
            #pragma unroll
            for (int nb = 0; nb < 4; nb++) {
                uint32_t bk[4];
                uint32_t off = cur + KK16 + bKp + (uint32_t)(nb * 16 * FP * 2) + ks * 32;
                ldsm_x4(bk, sb + off);
                mma16816h(sacc[2 * nb],     aq, &bk[0]);
                mma16816h(sacc[2 * nb + 1], aq, &bk[2]);
            }
        }

        // Register softmax (exp2 domain), fp16x2 exponentials
        float rmax0 = -1e30f, rmax1 = -1e30f;
        #pragma unroll
        for (int j = 0; j < 8; j++) {
            rmax0 = fmaxf(rmax0, fmaxf(sacc[j][0], sacc[j][1]));
            rmax1 = fmaxf(rmax1, fmaxf(sacc[j][2], sacc[j][3]));
        }
        rmax0 = fmaxf(rmax0, __shfl_xor_sync(0xffffffffu, rmax0, 1));
        rmax0 = fmaxf(rmax0, __shfl_xor_sync(0xffffffffu, rmax0, 2));
        rmax1 = fmaxf(rmax1, __shfl_xor_sync(0xffffffffu, rmax1, 1));
        rmax1 = fmaxf(rmax1, __shfl_xor_sync(0xffffffffu, rmax1, 2));
        float mn0 = fmaxf(mr0, rmax0), mn1 = fmaxf(mr1, rmax1);
        float al0 = exp2f(mr0 - mn0), al1 = exp2f(mr1 - mn1);

        // exp + pack P fragments + fp32 sums
        float sum0 = 0.0f, sum1 = 0.0f;
        uint32_t ph[4][4];
        #pragma unroll
        for (int k2 = 0; k2 < 4; k2++) {
            ph[k2][0] = pexp2(sacc[2*k2][0],   sacc[2*k2][1],   mn0, sum0);
            ph[k2][1] = pexp2(sacc[2*k2][2],   sacc[2*k2][3],   mn1, sum1);
            ph[k2][2] = pexp2(sacc[2*k2+1][0], sacc[2*k2+1][1], mn0, sum0);
            ph[k2][3] = pexp2(sacc[2*k2+1][2], sacc[2*k2+1][3], mn1, sum1);
        }
        sum0 += __shfl_xor_sync(0xffffffffu, sum0, 1);
        sum0 += __shfl_xor_sync(0xffffffffu, sum0, 2);
        sum1 += __shfl_xor_sync(0xffffffffu, sum1, 1);
        sum1 += __shfl_xor_sync(0xffffffffu, sum1, 2);
        lr0 = lr0 * al0 + sum0; mr0 = mn0;
        lr1 = lr1 * al1 + sum1; mr1 = mn1;

        #pragma unroll
        for (int j = 0; j < 8; j++) {
            oacc[j][0] *= al0; oacc[j][1] *= al0;
            oacc[j][2] *= al1; oacc[j][3] *= al1;
        }

        // O += P @ V (single-pass fp16; paired V fetch via ldmatrix.x4.trans)
        #pragma unroll
        for (int k2 = 0; k2 < 4; k2++) {
            #pragma unroll
            for (int nb = 0; nb < 4; nb++) {
                uint32_t bv[4];
                uint32_t off = cur + VV16 + bVp + (uint32_t)((k2 * 16 * FP + nb * 16) * 2);
                ldsm_x4t(bv, sb + off);
                mma16816h(oacc[2 * nb],     ph[k2], &bv[0]);
                mma16816h(oacc[2 * nb + 1], ph[k2], &bv[2]);
            }
        }

        if (kb < 15) CP_WAIT0();
        __syncthreads();
    }

    float il0 = 1.0f / lr0, il1 = 1.0f / lr1;
    int row0 = wm + g, row1 = wm + g + 8;
    #pragma unroll
    for (int na = 0; na < 8; na++) {
        int col = na * 8 + tq * 2;
        float v00 = oacc[na][0] * il0, v01 = oacc[na][1] * il0;
        float v10 = oacc[na][2] * il1, v11 = oacc[na][3] * il1;
        size_t o0 = baseQ + (size_t)row0 * Dq + col;
        size_t o1 = baseQ + (size_t)row1 * Dq + col;
        if (O) {
            *(float2*)&O[o0] = make_float2(v00, v01);
            *(float2*)&O[o1] = make_float2(v10, v11);
        }
        if (O16) {
            *(uint32_t*)&O16[o0] = pkh2(v00, v01);
            *(uint32_t*)&O16[o1] = pkh2(v10, v11);
        }
    }
}

// ---------------- launcher ----------------
extern "C" void kernel_launch(void* const* d_in, const int* in_sizes, int n_in,
                              void* d_out, int out_size) {
    const float* in0   = (const float*)d_in[0];
    const float* in1   = (const float*)d_in[1];
    const float* ge = (const float*)d_in[6];
    const float* be = (const float*)d_in[7];
    const float* gd = (const float*)d_in[12];
    const float* bd = (const float*)d_in[13];
    float* out = (float*)d_out;

    float *E, *DI, *Sb, *I;
    __half *A16, *Q16, *K16, *V16, *EO16, *EOq16, *W16;
    cudaGetSymbolAddress((void**)&E,     g_E);
    cudaGetSymbolAddress((void**)&DI,    g_DI);
    cudaGetSymbolAddress((void**)&Sb,    g_S);
    cudaGetSymbolAddress((void**)&I,     g_I);
    cudaGetSymbolAddress((void**)&A16,   g_A16);
    cudaGetSymbolAddress((void**)&Q16,   g_Q16);
    cudaGetSymbolAddress((void**)&K16,   g_K16);
    cudaGetSymbolAddress((void**)&V16,   g_V16);
    cudaGetSymbolAddress((void**)&EO16,  g_EO16);
    cudaGetSymbolAddress((void**)&EOq16, g_EOq16);
    cudaGetSymbolAddress((void**)&W16,   g_W16);

    cudaFuncSetAttribute(gemm_mma_kernel,  cudaFuncAttributeMaxDynamicSharedMemorySize, GEMM_SMEM);
    cudaFuncSetAttribute(gemm_qkv_kernel,  cudaFuncAttributeMaxDynamicSharedMemorySize, GEMM_SMEM);
    cudaFuncSetAttribute(flash_mma_kernel, cudaFuncAttributeMaxDynamicSharedMemorySize, FLASH_SMEM);

    dim3 ggrid(Dq / 128, BSr / 128);        // (4, 64)
    dim3 qkvgrid(3 * Dq / 128, BSr / 128);  // (12, 64)
    dim3 fgrid(Sq / 128, Hq, Bq);           // (8, 8, 8)
    const int WSZ = Dq * Dq;

    dim3 wgrid(WSZ / 256, 8);
    cvt_wt_all_kernel<<<wgrid, 256>>>(
        (const float*)d_in[2], (const float*)d_in[3], (const float*)d_in[4],
        (const float*)d_in[5], (const float*)d_in[8], (const float*)d_in[9],
        (const float*)d_in[10], (const float*)d_in[11], W16);

    // ---- Encoder ----
    add_pos_kernel<<<BSD / 256, 256>>>(in0, E, A16);
    gemm_qkv_kernel<<<qkvgrid, 256, GEMM_SMEM>>>(A16, W16, Q16, K16, V16);
    flash_mma_kernel<<<fgrid, 256, FLASH_SMEM>>>(Q16, K16, V16, Sb, nullptr);
    ln_add_kernel<<<BSr, 256>>>(Sb, ge, be, E, 1.0f, I, A16);
    gemm_mma_kernel<<<ggrid, 256, GEMM_SMEM>>>(A16, W16 + 3 * WSZ,
                                               E, nullptr, EO16, EOq16);   // enc_out (fp16 + scaled)

    // ---- Decoder ----
    add_pos_kernel<<<BSD / 256, 256>>>(in1, DI, A16);
    gemm_qkv_kernel<<<qkvgrid, 256, GEMM_SMEM>>>(A16, W16 + 4 * WSZ, Q16, K16, V16);
    flash_mma_kernel<<<fgrid, 256, FLASH_SMEM>>>(Q16, K16, V16, Sb, nullptr);
    ln_add_kernel<<<BSr, 256>>>(Sb, gd, bd, DI, 2.0f, I, nullptr);         // i2
    flash_mma_kernel<<<fgrid, 256, FLASH_SMEM>>>(EOq16, EO16, EO16, nullptr, A16);  // eda
    gemm_mma_kernel<<<ggrid, 256, GEMM_SMEM>>>(A16, W16 + 7 * WSZ,
                                               I, out, nullptr, nullptr);  // dec_out
}

// round 15
// speedup vs baseline: 1.0952x; 1.0952x over previous
#include <cuda_runtime.h>
#include <cuda_bf16.h>
#include <cuda_fp16.h>
#include <cstdint>
#include <math.h>

// Problem constants
#define Bq   8
#define Sq   1024
#define Dq   512
#define Hq   8
#define DHq  64
#define BSr  (Bq*Sq)        // 8192 rows
#define BSD  (Bq*Sq*Dq)     // 4194304 elements

#define LOG2E_DIV_H 0.18033688f    // log2(e)/8

// ---------------- device scratch (no allocations allowed) ----------------
__device__ float g_E  [BSD];
__device__ float g_DI [BSD];
__device__ float g_Se [BSD];
__device__ float g_Sd [BSD];
__device__ float g_I  [BSD];
__device__ __half g_Ae16[BSD], g_Ad16[BSD];
__device__ __half g_Qe16[BSD], g_Ke16[BSD], g_Ve16[BSD];
__device__ __half g_Qd16[BSD], g_Kd16[BSD], g_Vd16[BSD];
__device__ __half g_EO16[BSD];    // enc_out fp16 (K/V role in eda)
__device__ __half g_EOq16[BSD];   // enc_out fp16 pre-scaled (Q role in eda)
__device__ __half g_EDA16[BSD];   // eda output fp16
__device__ __half g_W16[8 * Dq * Dq];   // transposed weights [n][k], fp16

// ---------------- helpers (non-'a' ISA only) ----------------
__device__ __forceinline__ uint32_t smem_u32(const void* p) {
    uint32_t a;
    asm("{ .reg .u64 t; cvta.to.shared.u64 t, %1; cvt.u32.u64 %0, t; }" : "=r"(a) : "l"(p));
    return a;
}
__device__ __forceinline__ void ldsm_x4(uint32_t* r, uint32_t addr) {
    asm volatile("ldmatrix.sync.aligned.m8n8.x4.shared.b16 {%0,%1,%2,%3}, [%4];"
        : "=r"(r[0]), "=r"(r[1]), "=r"(r[2]), "=r"(r[3]) : "r"(addr));
}
__device__ __forceinline__ void ldsm_x4t(uint32_t* r, uint32_t addr) {
    asm volatile("ldmatrix.sync.aligned.m8n8.x4.trans.shared.b16 {%0,%1,%2,%3}, [%4];"
        : "=r"(r[0]), "=r"(r[1]), "=r"(r[2]), "=r"(r[3]) : "r"(addr));
}
__device__ __forceinline__ void mma16816h(float* c, const uint32_t* a, const uint32_t* b) {
    asm volatile("mma.sync.aligned.m16n8k16.row.col.f32.f16.f16.f32 "
        "{%0,%1,%2,%3}, {%4,%5,%6,%7}, {%8,%9}, {%0,%1,%2,%3};"
        : "+f"(c[0]), "+f"(c[1]), "+f"(c[2]), "+f"(c[3])
        : "r"(a[0]), "r"(a[1]), "r"(a[2]), "r"(a[3]), "r"(b[0]), "r"(b[1]));
}
__device__ __forceinline__ uint32_t pkh2(float a, float b) {
    __half2 h = __floats2half2_rn(a, b);
    return *(uint32_t*)&h;
}
#define CPA16(sa, gp) asm volatile("cp.async.cg.shared.global [%0], [%1], 16;" :: "r"(sa), "l"(gp))
#define CP_COMMIT()   asm volatile("cp.async.commit_group;")
#define CP_WAIT0()    asm volatile("cp.async.wait_group 0;" ::: "memory")

// ---------------- fused weight convert + transpose (all 8, fp16) ----------------
__global__ void __launch_bounds__(256) cvt_wt_all_kernel(
    const float* __restrict__ W0, const float* __restrict__ W1,
    const float* __restrict__ W2, const float* __restrict__ W3,
    const float* __restrict__ W4, const float* __restrict__ W5,
    const float* __restrict__ W6, const float* __restrict__ W7,
    __half* __restrict__ o16) {
    int w = blockIdx.y;
    const float* W = (w == 0) ? W0 : (w == 1) ? W1 : (w == 2) ? W2 : (w == 3) ? W3 :
                     (w == 4) ? W4 : (w == 5) ? W5 : (w == 6) ? W6 : W7;
    int idx = blockIdx.x * 256 + threadIdx.x;   // idx = n*512 + k
    int n = idx >> 9, k = idx & 511;
    o16[(size_t)w * Dq * Dq + idx] = __float2half_rn(W[k * Dq + n]);
}

// ---------------- positional-embedding add, enc+dec fused ----------------
__global__ void __launch_bounds__(256) add_pos2_kernel(const float* __restrict__ x0,
                                                       const float* __restrict__ x1,
                                                       float* __restrict__ out0,
                                                       float* __restrict__ out1,
                                                       __half* __restrict__ o0,
                                                       __half* __restrict__ o1) {
    int idx = blockIdx.x * 256 + threadIdx.x;
    const float* x = blockIdx.y ? x1 : x0;
    float* out     = blockIdx.y ? out1 : out0;
    __half* o16    = blockIdx.y ? o1 : o0;
    int d = idx & (Dq - 1);
    int s = (idx >> 9) & (Sq - 1);
    float freq  = expf((float)d * -0.0359778920794f);
    float angle = (float)s * freq;
    float pe = (d & 1) ? cosf(angle) : sinf(angle);
    float r = x[idx] + pe;
    out[idx] = r;
    o16[idx] = __float2half_rn(r);
}

// ---------------- fused LayerNorm + residual, enc+dec fused ----------------
__global__ void __launch_bounds__(256) ln_add2_kernel(
    const float* __restrict__ xe, const float* __restrict__ xd,
    const float* __restrict__ ge, const float* __restrict__ be,
    const float* __restrict__ gd, const float* __restrict__ bd,
    const float* __restrict__ basee, const float* __restrict__ based,
    float* __restrict__ outd, __half* __restrict__ o16e) {
    __shared__ float red[256];
    int t = threadIdx.x;
    int z = blockIdx.y;
    size_t off = (size_t)blockIdx.x * Dq;
    const float* x     = z ? xd : xe;
    const float* gamma = z ? gd : ge;
    const float* beta  = z ? bd : be;
    const float* basep = z ? based : basee;
    float scale        = z ? 2.0f : 1.0f;

    float v0 = x[off + t];
    float v1 = x[off + t + 256];

    red[t] = v0 + v1;
    __syncthreads();
    #pragma unroll
    for (int s2 = 128; s2 > 0; s2 >>= 1) {
        if (t < s2) red[t] += red[t + s2];
        __syncthreads();
    }
    float mu = red[0] * (1.0f / 512.0f);
    __syncthreads();

    float d0 = v0 - mu, d1 = v1 - mu;
    red[t] = d0 * d0 + d1 * d1;
    __syncthreads();
    #pragma unroll
    for (int s2 = 128; s2 > 0; s2 >>= 1) {
        if (t < s2) red[t] += red[t + s2];
        __syncthreads();
    }
    float var = red[0] * (1.0f / 512.0f);
    float rs  = rsqrtf(var + 1e-3f);

    float r0 = basep[off + t]       + scale * (d0 * rs * gamma[t]       + beta[t]);
    float r1 = basep[off + t + 256] + scale * (d1 * rs * gamma[t + 256] + beta[t + 256]);
    if (z) {   // decoder: i2, fp32 (addend of final GEMM)
        outd[off + t]       = r0;
        outd[off + t + 256] = r1;
    } else {   // encoder: inter_e, fp16 (input of FF GEMM)
        o16e[off + t]       = __float2half_rn(r0);
        o16e[off + t + 256] = __float2half_rn(r1);
    }
}

// ---------------- GEMM core: 128x128 tile, fp16 single pass ----------------
#define APAD 72
#define SA16 0
#define SB16 18432
#define GEMM_SMEM 36864

struct GemmFrag { float acc[2][8][4]; };

__device__ __forceinline__ void gemm_core(uint32_t sb, char* smem,
                                          const __half* __restrict__ A16,
                                          const __half* __restrict__ B16,
                                          int m0, int n0, GemmFrag& F) {
    __half* sA = (__half*)(smem + SA16);
    __half* sB = (__half*)(smem + SB16);

    int tid = threadIdx.x;
    int wid = tid >> 5, lane = tid & 31;
    int wm = (wid & 3) * 32;
    int wn = (wid >> 2) * 64;

    #pragma unroll
    for (int i = 0; i < 2; i++)
        #pragma unroll
        for (int j = 0; j < 8; j++)
            #pragma unroll
            for (int q = 0; q < 4; q++) F.acc[i][j][q] = 0.0f;

    int la = lane & 15;
    int lacol = (lane >> 4) << 3;
    int nrow = (lane & 7) + ((lane >> 4) << 3);
    int koff = ((lane >> 3) & 1) << 3;

    int rT = tid >> 1, cT = (tid & 1) * 32;

    for (int kc = 0; kc < 8; kc++) {
        int kofs = kc * 64;
        #pragma unroll
        for (int q = 0; q < 4; q++) {
            size_t goA = (size_t)(m0 + rT) * Dq + kofs + cT + q * 8;
            size_t goB = (size_t)(n0 + rT) * Dq + kofs + cT + q * 8;
            *(uint4*)&sA[rT * APAD + cT + q * 8] = *(const uint4*)&A16[goA];
            *(uint4*)&sB[rT * APAD + cT + q * 8] = *(const uint4*)&B16[goB];
        }
        __syncthreads();

        #pragma unroll
        for (int ks = 0; ks < 4; ks++) {
            int kk = ks * 16;
            uint32_t a[2][4];
            #pragma unroll
            for (int ma = 0; ma < 2; ma++) {
                int row = wm + ma * 16 + la;
                ldsm_x4(a[ma], sb + SA16 + (uint32_t)((row * APAD + kk + lacol) * 2));
            }
            uint32_t bq[4][4];
            #pragma unroll
            for (int nb = 0; nb < 4; nb++) {
                int rown = wn + nb * 16 + nrow;
                ldsm_x4(bq[nb], sb + SB16 + (uint32_t)((rown * APAD + kk + koff) * 2));
            }
            #pragma unroll
            for (int ma = 0; ma < 2; ma++)
                #pragma unroll
                for (int nb = 0; nb < 4; nb++) {
                    mma16816h(F.acc[ma][2 * nb],     a[ma], &bq[nb][0]);
                    mma16816h(F.acc[ma][2 * nb + 1], a[ma], &bq[nb][2]);
                }
        }
        __syncthreads();
    }
}

// ---- generic GEMM: fp32 out (+addend) and/or fp16 out (+scaled fp16 copy) ----
__global__ void __launch_bounds__(256) gemm_mma_kernel(
    const __half* __restrict__ A16, const __half* __restrict__ B16,
    const float* __restrict__ addend, float* __restrict__ C,
    __half* __restrict__ C16, __half* __restrict__ C16s) {
    extern __shared__ char smem[];
    uint32_t sb = smem_u32(smem);
    int m0 = blockIdx.y * 128, n0 = blockIdx.x * 128;
    GemmFrag F;
    gemm_core(sb, smem, A16, B16, m0, n0, F);

    int wid = threadIdx.x >> 5, lane = threadIdx.x & 31;
    int wm = (wid & 3) * 32, wn = (wid >> 2) * 64;
    int g = lane >> 2, tq = lane & 3;
    #pragma unroll
    for (int ma = 0; ma < 2; ma++) {
        int row = m0 + wm + ma * 16 + g;
        #pragma unroll
        for (int na = 0; na < 8; na++) {
            int col = n0 + wn + na * 8 + tq * 2;
            size_t o0 = (size_t)row * Dq + col;
            size_t o1 = o0 + 8 * Dq;
            float2 r0 = make_float2(F.acc[ma][na][0], F.acc[ma][na][1]);
            float2 r1 = make_float2(F.acc[ma][na][2], F.acc[ma][na][3]);
            if (addend) {
                float2 a0 = *(const float2*)&addend[o0];
                float2 a1 = *(const float2*)&addend[o1];
                r0.x += a0.x; r0.y += a0.y;
                r1.x += a1.x; r1.y += a1.y;
            }
            if (C) {
                *(float2*)&C[o0] = r0;
                *(float2*)&C[o1] = r1;
            }
            if (C16) {
                *(uint32_t*)&C16[o0] = pkh2(r0.x, r0.y);
                *(uint32_t*)&C16[o1] = pkh2(r1.x, r1.y);
            }
            if (C16s) {
                *(uint32_t*)&C16s[o0] = pkh2(r0.x * LOG2E_DIV_H, r0.y * LOG2E_DIV_H);
                *(uint32_t*)&C16s[o1] = pkh2(r1.x * LOG2E_DIV_H, r1.y * LOG2E_DIV_H);
            }
        }
    }
}

// ---- fused QKV GEMM for BOTH enc and dec (6 weights); Q outputs pre-scaled ----
__global__ void __launch_bounds__(256) gemm_qkv6_kernel(
    const __half* __restrict__ Ae, const __half* __restrict__ Ad,
    const __half* __restrict__ W16,
    __half* __restrict__ Qe, __half* __restrict__ Ke, __half* __restrict__ Ve,
    __half* __restrict__ Qd, __half* __restrict__ Kd, __half* __restrict__ Vd) {
    extern __shared__ char smem[];
    uint32_t sb = smem_u32(smem);
    int w = blockIdx.x >> 2;                 // 0..5: encQ,encK,encV,decQ,decK,decV
    int n0 = (blockIdx.x & 3) * 128;
    int m0 = blockIdx.y * 128;
    const __half* A16 = (w < 3) ? Ae : Ad;
    int widx = (w < 3) ? w : (w + 1);        // weights 0,1,2 enc; 4,5,6 dec
    const __half* B16 = W16 + (size_t)widx * Dq * Dq;
    __half* O16 = (w == 0) ? Qe : (w == 1) ? Ke : (w == 2) ? Ve :
                  (w == 3) ? Qd : (w == 4) ? Kd : Vd;
    float sc = (w == 0 || w == 3) ? LOG2E_DIV_H : 1.0f;

    GemmFrag F;
    gemm_core(sb, smem, A16, B16, m0, n0, F);

    int wid = threadIdx.x >> 5, lane = threadIdx.x & 31;
    int wm = (wid & 3) * 32, wn = (wid >> 2) * 64;
    int g = lane >> 2, tq = lane & 3;
    #pragma unroll
    for (int ma = 0; ma < 2; ma++) {
        int row = m0 + wm + ma * 16 + g;
        #pragma unroll
        for (int na = 0; na < 8; na++) {
            int col = n0 + wn + na * 8 + tq * 2;
            size_t o0 = (size_t)row * Dq + col;
            size_t o1 = o0 + 8 * Dq;
            *(uint32_t*)&O16[o0] = pkh2(F.acc[ma][na][0] * sc, F.acc[ma][na][1] * sc);
            *(uint32_t*)&O16[o1] = pkh2(F.acc[ma][na][2] * sc, F.acc[ma][na][3] * sc);
        }
    }
}

// ---------------- flash attention: enc+dec fused, 128q, fp16, dbuf KV, paired LDSM ----------------
// Q pre-scaled by LOG2E_DIV_H -> scores directly in exp2 domain. R13 softmax (proven).
#define FP 72
#define FQ16 0
#define FKV  18432
#define KK16 0
#define VV16 9216
#define KVBUF 18432
#define FLASH_SMEM (FKV + 2 * KVBUF)   // 55296 -> 2 CTAs/SM

__global__ void __launch_bounds__(256) flash2_mma_kernel(
    const __half* __restrict__ Qe, const __half* __restrict__ Ke, const __half* __restrict__ Ve,
    const __half* __restrict__ Qd, const __half* __restrict__ Kd, const __half* __restrict__ Vd,
    float* __restrict__ Oe, float* __restrict__ Od) {
    extern __shared__ char smem[];
    uint32_t sb = smem_u32(smem);

    int tid = threadIdx.x, wid = tid >> 5, lane = tid & 31;
    int wm = wid * 16;
    int g = lane >> 2, tq = lane & 3;
    int qb = blockIdx.x, h = blockIdx.y;
    int bz = blockIdx.z;
    int isd = bz >> 3;           // 0 = enc, 1 = dec
    int b = bz & 7;
    const __half* Q16 = isd ? Qd : Qe;
    const __half* K16 = isd ? Kd : Ke;
    const __half* V16 = isd ? Vd : Ve;
    float* O = isd ? Od : Oe;
    size_t baseQ  = ((size_t)b * Sq + (size_t)qb * 128) * Dq + h * DHq;
    size_t baseKV = (size_t)b * Sq * Dq + h * DHq;

    int rQ = tid >> 1, cQ = (tid & 1) * 32;
    int rK = tid >> 2, cK = (tid & 3) * 16;

    auto kvload = [&](int kb, uint32_t bofs) {
        size_t go = baseKV + (size_t)(kb * 64 + rK) * Dq + cK;
        uint32_t so = sb + FKV + bofs + (uint32_t)((rK * FP + cK) * 2);
        #pragma unroll
        for (int q = 0; q < 2; q++) {
            CPA16(so + KK16 + q * 16, &K16[go + q * 8]);
            CPA16(so + VV16 + q * 16, &V16[go + q * 8]);
        }
    };

    {   // Q + KV tile 0
        size_t go = baseQ + (size_t)rQ * Dq + cQ;
        uint32_t so = sb + FQ16 + (uint32_t)((rQ * FP + cQ) * 2);
        #pragma unroll
        for (int q = 0; q < 4; q++)
            CPA16(so + q * 16, &Q16[go + q * 8]);
        kvload(0, 0);
        CP_COMMIT();
        CP_WAIT0();
        __syncthreads();
    }

    float oacc[8][4];
    #pragma unroll
    for (int j = 0; j < 8; j++)
        #pragma unroll
        for (int q = 0; q < 4; q++) oacc[j][q] = 0.0f;
    float mr0 = -1e30f, mr1 = -1e30f, lr0 = 0.0f, lr1 = 0.0f;

    uint32_t aQ = (uint32_t)(((wm + (lane & 15)) * FP + ((lane >> 4) << 3)) * 2);
    int nrow = (lane & 7) + ((lane >> 4) << 3);
    int koff = ((lane >> 3) & 1) << 3;
    uint32_t bKp = (uint32_t)((nrow * FP + koff) * 2);
    uint32_t bVp = (uint32_t)(((lane & 15) * FP + ((lane >> 4) << 3)) * 2);

    for (int kb = 0; kb < 16; kb++) {
        uint32_t cur = FKV + ((kb & 1) ? KVBUF : 0);
        if (kb < 15) {
            kvload(kb + 1, (kb & 1) ? 0 : KVBUF);
            CP_COMMIT();
        }

        // S = Q @ K^T (single-pass fp16, paired B fetch); scores in exp2 domain
        float sacc[8][4];
        #pragma unroll
        for (int j = 0; j < 8; j++)
            #pragma unroll
            for (int q = 0; q < 4; q++) sacc[j][q] = 0.0f;

        #pragma unroll
        for (int ks = 0; ks < 4; ks++) {
            uint32_t aq[4];
            ldsm_x4(aq, sb + FQ16 + aQ + ks * 32);
            #pragma unroll
            for (int nb = 0; nb < 4; nb++) {
                uint32_t bk[4];
                uint32_t off = cur + KK16 + bKp + (uint32_t)(nb * 16 * FP * 2) + ks * 32;
                ldsm_x4(bk, sb + off);
                mma16816h(sacc[2 * nb],     aq, &bk[0]);
                mma16816h(sacc[2 * nb + 1], aq, &bk[2]);
            }
        }

        // Register softmax (R13 form: fp32 exp2f + pkh2)
        float rmax0 = -1e30f, rmax1 = -1e30f;
        #pragma unroll
        for (int j = 0; j < 8; j++) {
            rmax0 = fmaxf(rmax0, fmaxf(sacc[j][0], sacc[j][1]));
            rmax1 = fmaxf(rmax1, fmaxf(sacc[j][2], sacc[j][3]));
        }
        rmax0 = fmaxf(rmax0, __shfl_xor_sync(0xffffffffu, rmax0, 1));
        rmax0 = fmaxf(rmax0, __shfl_xor_sync(0xffffffffu, rmax0, 2));
        rmax1 = fmaxf(rmax1, __shfl_xor_sync(0xffffffffu, rmax1, 1));
        rmax1 = fmaxf(rmax1, __shfl_xor_sync(0xffffffffu, rmax1, 2));
        float mn0 = fmaxf(mr0, rmax0), mn1 = fmaxf(mr1, rmax1);
        float al0 = exp2f(mr0 - mn0), al1 = exp2f(mr1 - mn1);
        float sum0 = 0.0f, sum1 = 0.0f;
        #pragma unroll
        for (int j = 0; j < 8; j++) {
            sacc[j][0] = exp2f(sacc[j][0] - mn0);
            sacc[j][1] = exp2f(sacc[j][1] - mn0);
            sacc[j][2] = exp2f(sacc[j][2] - mn1);
            sacc[j][3] = exp2f(sacc[j][3] - mn1);
            sum0 += sacc[j][0] + sacc[j][1];
            sum1 += sacc[j][2] + sacc[j][3];
        }
        sum0 += __shfl_xor_sync(0xffffffffu, sum0, 1);
        sum0 += __shfl_xor_sync(0xffffffffu, sum0, 2);
        sum1 += __shfl_xor_sync(0xffffffffu, sum1, 1);
        sum1 += __shfl_xor_sync(0xffffffffu, sum1, 2);
        lr0 = lr0 * al0 + sum0; mr0 = mn0;
        lr1 = lr1 * al1 + sum1; mr1 = mn1;

        #pragma unroll
        for (int j = 0; j < 8; j++) {
            oacc[j][0] *= al0; oacc[j][1] *= al0;
            oacc[j][2] *= al1; oacc[j][3] *= al1;
        }

        uint32_t ph[4][4];
        #pragma unroll
        for (int k2 = 0; k2 < 4; k2++) {
            ph[k2][0] = pkh2(sacc[2*k2][0],   sacc[2*k2][1]);
            ph[k2][1] = pkh2(sacc[2*k2][2],   sacc[2*k2][3]);
            ph[k2][2] = pkh2(sacc[2*k2+1][0], sacc[2*k2+1][1]);
            ph[k2][3] = pkh2(sacc[2*k2+1][2], sacc[2*k2+1][3]);
        }

        // O += P @ V
        #pragma unroll
        for (int k2 = 0; k2 < 4; k2++) {
            #pragma unroll
            for (int nb = 0; nb < 4; nb++) {
                uint32_t bv[4];
                uint32_t off = cur + VV16 + bVp + (uint32_t)((k2 * 16 * FP + nb * 16) * 2);
                ldsm_x4t(bv, sb + off);
                mma16816h(oacc[2 * nb],     ph[k2], &bv[0]);
                mma16816h(oacc[2 * nb + 1], ph[k2], &bv[2]);
            }
        }

        if (kb < 15) CP_WAIT0();
        __syncthreads();
    }

    float il0 = 1.0f / lr0, il1 = 1.0f / lr1;
    int row0 = wm + g, row1 = wm + g + 8;
    #pragma unroll
    for (int na = 0; na < 8; na++) {
        int col = na * 8 + tq * 2;
        size_t o0 = baseQ + (size_t)row0 * Dq + col;
        size_t o1 = baseQ + (size_t)row1 * Dq + col;
        *(float2*)&O[o0] = make_float2(oacc[na][0] * il0, oacc[na][1] * il0);
        *(float2*)&O[o1] = make_float2(oacc[na][2] * il1, oacc[na][3] * il1);
    }
}

// ---- single flash for eda (fp16 out), R13-style ----
__global__ void __launch_bounds__(256) flash_mma_kernel(
    const __half* __restrict__ Q16,
    const __half* __restrict__ K16,
    const __half* __restrict__ V16,
    __half* __restrict__ O16) {
    extern __shared__ char smem[];
    uint32_t sb = smem_u32(smem);

    int tid = threadIdx.x, wid = tid >> 5, lane = tid & 31;
    int wm = wid * 16;
    int g = lane >> 2, tq = lane & 3;
    int qb = blockIdx.x, h = blockIdx.y, b = blockIdx.z;
    size_t baseQ  = ((size_t)b * Sq + (size_t)qb * 128) * Dq + h * DHq;
    size_t baseKV = (size_t)b * Sq * Dq + h * DHq;

    int rQ = tid >> 1, cQ = (tid & 1) * 32;
    int rK = tid >> 2, cK = (tid & 3) * 16;

    auto kvload = [&](int kb, uint32_t bofs) {
        size_t go = baseKV + (size_t)(kb * 64 + rK) * Dq + cK;
        uint32_t so = sb + FKV + bofs + (uint32_t)((rK * FP + cK) * 2);
        #pragma unroll
        for (int q = 0; q < 2; q++) {
            CPA16(so + KK16 + q * 16, &K16[go + q * 8]);
            CPA16(so + VV16 + q * 16, &V16[go + q * 8]);
        }
    };

    {
        size_t go = baseQ + (size_t)rQ * Dq + cQ;
        uint32_t so = sb + FQ16 + (uint32_t)((rQ * FP + cQ) * 2);
        #pragma unroll
        for (int q = 0; q < 4; q++)
            CPA16(so + q * 16, &Q16[go + q * 8]);
        kvload(0, 0);
        CP_COMMIT();
        CP_WAIT0();
        __syncthreads();
    }

    float oacc[8][4];
    #pragma unroll
    for (int j = 0; j < 8; j++)
        #pragma unroll
        for (int q = 0; q < 4; q++) oacc[j][q] = 0.0f;
    float mr0 = -1e30f, mr1 = -1e30f, lr0 = 0.0f, lr1 = 0.0f;

    uint32_t aQ = (uint32_t)(((wm + (lane & 15)) * FP + ((lane >> 4) << 3)) * 2);
    int nrow = (lane & 7) + ((lane >> 4) << 3);
    int koff = ((lane >> 3) & 1) << 3;
    uint32_t bKp = (uint32_t)((nrow * FP + koff) * 2);
    uint32_t bVp = (uint32_t)(((lane & 15) * FP + ((lane >> 4) << 3)) * 2);

    for (int kb = 0; kb < 16; kb++) {
        uint32_t cur = FKV + ((kb & 1) ? KVBUF : 0);
        if (kb < 15) {
            kvload(kb + 1, (kb & 1) ? 0 : KVBUF);
            CP_COMMIT();
        }

        float sacc[8][4];
        #pragma unroll
        for (int j = 0; j < 8; j++)
            #pragma unroll
            for (int q = 0; q < 4; q++) sacc[j][q] = 0.0f;

        #pragma unroll
        for (int ks = 0; ks < 4; ks++) {
            uint32_t aq[4];
            ldsm_x4(aq, sb + FQ16 + aQ + ks * 32);
            #pragma unroll
            for (int nb = 0; nb < 4; nb++) {
                uint32_t bk[4];
                uint32_t off = cur + KK16 + bKp + (uint32_t)(nb * 16 * FP * 2) + ks * 32;
                ldsm_x4(bk, sb + off);
                mma16816h(sacc[2 * nb],     aq, &bk[0]);
                mma16816h(sacc[2 * nb + 1], aq, &bk[2]);
            }
        }

        float rmax0 = -1e30f, rmax1 = -1e30f;
        #pragma unroll
        for (int j = 0; j < 8; j++) {
            rmax0 = fmaxf(rmax0, fmaxf(sacc[j][0], sacc[j][1]));
            rmax1 = fmaxf(rmax1, fmaxf(sacc[j][2], sacc[j][3]));
        }
        rmax0 = fmaxf(rmax0, __shfl_xor_sync(0xffffffffu, rmax0, 1));
        rmax0 = fmaxf(rmax0, __shfl_xor_sync(0xffffffffu, rmax0, 2));
        rmax1 = fmaxf(rmax1, __shfl_xor_sync(0xffffffffu, rmax1, 1));
        rmax1 = fmaxf(rmax1, __shfl_xor_sync(0xffffffffu, rmax1, 2));
        float mn0 = fmaxf(mr0, rmax0), mn1 = fmaxf(mr1, rmax1);
        float al0 = exp2f(mr0 - mn0), al1 = exp2f(mr1 - mn1);
        float sum0 = 0.0f, sum1 = 0.0f;
        #pragma unroll
        for (int j = 0; j < 8; j++) {
            sacc[j][0] = exp2f(sacc[j][0] - mn0);
            sacc[j][1] = exp2f(sacc[j][1] - mn0);
            sacc[j][2] = exp2f(sacc[j][2] - mn1);
            sacc[j][3] = exp2f(sacc[j][3] - mn1);
            sum0 += sacc[j][0] + sacc[j][1];
            sum1 += sacc[j][2] + sacc[j][3];
        }
        sum0 += __shfl_xor_sync(0xffffffffu, sum0, 1);
        sum0 += __shfl_xor_sync(0xffffffffu, sum0, 2);
        sum1 += __shfl_xor_sync(0xffffffffu, sum1, 1);
        sum1 += __shfl_xor_sync(0xffffffffu, sum1, 2);
        lr0 = lr0 * al0 + sum0; mr0 = mn0;
        lr1 = lr1 * al1 + sum1; mr1 = mn1;

        #pragma unroll
        for (int j = 0; j < 8; j++) {
            oacc[j][0] *= al0; oacc[j][1] *= al0;
            oacc[j][2] *= al1; oacc[j][3] *= al1;
        }

        uint32_t ph[4][4];
        #pragma unroll
        for (int k2 = 0; k2 < 4; k2++) {
            ph[k2][0] = pkh2(sacc[2*k2][0],   sacc[2*k2][1]);
            ph[k2][1] = pkh2(sacc[2*k2][2],   sacc[2*k2][3]);
            ph[k2][2] = pkh2(sacc[2*k2+1][0], sacc[2*k2+1][1]);
            ph[k2][3] = pkh2(sacc[2*k2+1][2], sacc[2*k2+1][3]);
        }

        #pragma unroll
        for (int k2 = 0; k2 < 4; k2++) {
            #pragma unroll
            for (int nb = 0; nb < 4; nb++) {
                uint32_t bv[4];
                uint32_t off = cur + VV16 + bVp + (uint32_t)((k2 * 16 * FP + nb * 16) * 2);
                ldsm_x4t(bv, sb + off);
                mma16816h(oacc[2 * nb],     ph[k2], &bv[0]);
                mma16816h(oacc[2 * nb + 1], ph[k2], &bv[2]);
            }
        }

        if (kb < 15) CP_WAIT0();
        __syncthreads();
    }

    float il0 = 1.0f / lr0, il1 = 1.0f / lr1;
    int row0 = wm + g, row1 = wm + g + 8;
    #pragma unroll
    for (int na = 0; na < 8; na++) {
        int col = na * 8 + tq * 2;
        size_t o0 = baseQ + (size_t)row0 * Dq + col;
        size_t o1 = baseQ + (size_t)row1 * Dq + col;
        *(uint32_t*)&O16[o0] = pkh2(oacc[na][0] * il0, oacc[na][1] * il0);
        *(uint32_t*)&O16[o1] = pkh2(oacc[na][2] * il1, oacc[na][3] * il1);
    }
}

// ---------------- launcher ----------------
extern "C" void kernel_launch(void* const* d_in, const int* in_sizes, int n_in,
                              void* d_out, int out_size) {
    const float* in0 = (const float*)d_in[0];
    const float* in1 = (const float*)d_in[1];
    const float* ge = (const float*)d_in[6];
    const float* be = (const float*)d_in[7];
    const float* gd = (const float*)d_in[12];
    const float* bd = (const float*)d_in[13];
    float* out = (float*)d_out;

    float *E, *DI, *Se, *Sd, *I;
    __half *Ae, *Ad, *Qe, *Ke, *Ve, *Qd, *Kd, *Vd, *EO16, *EOq16, *EDA16, *W16;
    cudaGetSymbolAddress((void**)&E,     g_E);
    cudaGetSymbolAddress((void**)&DI,    g_DI);
    cudaGetSymbolAddress((void**)&Se,    g_Se);
    cudaGetSymbolAddress((void**)&Sd,    g_Sd);
    cudaGetSymbolAddress((void**)&I,     g_I);
    cudaGetSymbolAddress((void**)&Ae,    g_Ae16);
    cudaGetSymbolAddress((void**)&Ad,    g_Ad16);
    cudaGetSymbolAddress((void**)&Qe,    g_Qe16);
    cudaGetSymbolAddress((void**)&Ke,    g_Ke16);
    cudaGetSymbolAddress((void**)&Ve,    g_Ve16);
    cudaGetSymbolAddress((void**)&Qd,    g_Qd16);
    cudaGetSymbolAddress((void**)&Kd,    g_Kd16);
    cudaGetSymbolAddress((void**)&Vd,    g_Vd16);
    cudaGetSymbolAddress((void**)&EO16,  g_EO16);
    cudaGetSymbolAddress((void**)&EOq16, g_EOq16);
    cudaGetSymbolAddress((void**)&EDA16, g_EDA16);
    cudaGetSymbolAddress((void**)&W16,   g_W16);

    cudaFuncSetAttribute(gemm_mma_kernel,   cudaFuncAttributeMaxDynamicSharedMemorySize, GEMM_SMEM);
    cudaFuncSetAttribute(gemm_qkv6_kernel,  cudaFuncAttributeMaxDynamicSharedMemorySize, GEMM_SMEM);
    cudaFuncSetAttribute(flash2_mma_kernel, cudaFuncAttributeMaxDynamicSharedMemorySize, FLASH_SMEM);
    cudaFuncSetAttribute(flash_mma_kernel,  cudaFuncAttributeMaxDynamicSharedMemorySize, FLASH_SMEM);

    dim3 ggrid(Dq / 128, BSr / 128);        // (4, 64)
    dim3 qkv6grid(6 * Dq / 128, BSr / 128); // (24, 64)
    dim3 f2grid(Sq / 128, Hq, 2 * Bq);      // (8, 8, 16)
    dim3 fgrid(Sq / 128, Hq, Bq);           // (8, 8, 8)
    const int WSZ = Dq * Dq;

    dim3 wgrid(WSZ / 256, 8);
    cvt_wt_all_kernel<<<wgrid, 256>>>(
        (const float*)d_in[2], (const float*)d_in[3], (const float*)d_in[4],
        (const float*)d_in[5], (const float*)d_in[8], (const float*)d_in[9],
        (const float*)d_in[10], (const float*)d_in[11], W16);

    // enc_in + dec_in together
    dim3 pgrid(BSD / 256, 2);
    add_pos2_kernel<<<pgrid, 256>>>(in0, in1, E, DI, Ae, Ad);

    // all six QKV projections in one launch
    gemm_qkv6_kernel<<<qkv6grid, 256, GEMM_SMEM>>>(Ae, Ad, W16, Qe, Ke, Ve, Qd, Kd, Vd);

    // enc + dec self-attention in one launch
    flash2_mma_kernel<<<f2grid, 256, FLASH_SMEM>>>(Qe, Ke, Ve, Qd, Kd, Vd, Se, Sd);

    // both LayerNorms in one launch (enc -> Ae fp16; dec -> I fp32)
    dim3 lgrid(BSr, 2);
    ln_add2_kernel<<<lgrid, 256>>>(Se, Sd, ge, be, gd, bd, E, DI, I, Ae);

    // enc FF: enc_out = inter_e @ Wff_e + enc_in (fp16 + scaled fp16)
    gemm_mma_kernel<<<ggrid, 256, GEMM_SMEM>>>(Ae, W16 + 3 * WSZ, E, nullptr, EO16, EOq16);

    // eda (Q=K=V=enc_out)
    flash_mma_kernel<<<fgrid, 256, FLASH_SMEM>>>(EOq16, EO16, EO16, EDA16);

    // dec_out = eda @ Wff_d + i2
    gemm_mma_kernel<<<ggrid, 256, GEMM_SMEM>>>(EDA16, W16 + 7 * WSZ, I, out, nullptr, nullptr);
}

// round 16
// speedup vs baseline: 1.1324x; 1.0340x over previous
#include <cuda_runtime.h>
#include <cuda_bf16.h>
#include <cuda_fp16.h>
#include <cstdint>
#include <math.h>

// Problem constants
#define Bq   8
#define Sq   1024
#define Dq   512
#define Hq   8
#define DHq  64
#define BSr  (Bq*Sq)        // 8192 rows
#define BSD  (Bq*Sq*Dq)     // 4194304 elements

#define LOG2E_DIV_H 0.18033688f    // log2(e)/8

// ---------------- device scratch (no allocations allowed) ----------------
__device__ float g_E  [BSD];
__device__ float g_DI [BSD];
__device__ float g_Se [BSD];
__device__ float g_Sd [BSD];
__device__ float g_I  [BSD];
__device__ __half g_Ae16[BSD], g_Ad16[BSD];
__device__ __half g_Qe16[BSD], g_Ke16[BSD], g_Ve16[BSD];
__device__ __half g_Qd16[BSD], g_Kd16[BSD], g_Vd16[BSD];
__device__ __half g_EO16[BSD];
__device__ __half g_EOq16[BSD];
__device__ __half g_EDA16[BSD];
__device__ __half g_W16[8 * Dq * Dq];   // transposed weights [n][k], fp16

// ---------------- helpers (non-'a' ISA only) ----------------
__device__ __forceinline__ uint32_t smem_u32(const void* p) {
    uint32_t a;
    asm("{ .reg .u64 t; cvta.to.shared.u64 t, %1; cvt.u32.u64 %0, t; }" : "=r"(a) : "l"(p));
    return a;
}
__device__ __forceinline__ void ldsm_x4(uint32_t* r, uint32_t addr) {
    asm volatile("ldmatrix.sync.aligned.m8n8.x4.shared.b16 {%0,%1,%2,%3}, [%4];"
        : "=r"(r[0]), "=r"(r[1]), "=r"(r[2]), "=r"(r[3]) : "r"(addr));
}
__device__ __forceinline__ void ldsm_x4t(uint32_t* r, uint32_t addr) {
    asm volatile("ldmatrix.sync.aligned.m8n8.x4.trans.shared.b16 {%0,%1,%2,%3}, [%4];"
        : "=r"(r[0]), "=r"(r[1]), "=r"(r[2]), "=r"(r[3]) : "r"(addr));
}
__device__ __forceinline__ void mma16816h(float* c, const uint32_t* a, const uint32_t* b) {
    asm volatile("mma.sync.aligned.m16n8k16.row.col.f32.f16.f16.f32 "
        "{%0,%1,%2,%3}, {%4,%5,%6,%7}, {%8,%9}, {%0,%1,%2,%3};"
        : "+f"(c[0]), "+f"(c[1]), "+f"(c[2]), "+f"(c[3])
        : "r"(a[0]), "r"(a[1]), "r"(a[2]), "r"(a[3]), "r"(b[0]), "r"(b[1]));
}
__device__ __forceinline__ uint32_t pkh2(float a, float b) {
    __half2 h = __floats2half2_rn(a, b);
    return *(uint32_t*)&h;
}
#define CPA16(sa, gp) asm volatile("cp.async.cg.shared.global [%0], [%1], 16;" :: "r"(sa), "l"(gp))
#define CP_COMMIT()   asm volatile("cp.async.commit_group;")
#define CP_WAIT0()    asm volatile("cp.async.wait_group 0;" ::: "memory")

// ---------------- fused weight convert + transpose (all 8, fp16) ----------------
__global__ void __launch_bounds__(256) cvt_wt_all_kernel(
    const float* __restrict__ W0, const float* __restrict__ W1,
    const float* __restrict__ W2, const float* __restrict__ W3,
    const float* __restrict__ W4, const float* __restrict__ W5,
    const float* __restrict__ W6, const float* __restrict__ W7,
    __half* __restrict__ o16) {
    int w = blockIdx.y;
    const float* W = (w == 0) ? W0 : (w == 1) ? W1 : (w == 2) ? W2 : (w == 3) ? W3 :
                     (w == 4) ? W4 : (w == 5) ? W5 : (w == 6) ? W6 : W7;
    int idx = blockIdx.x * 256 + threadIdx.x;   // idx = n*512 + k
    int n = idx >> 9, k = idx & 511;
    o16[(size_t)w * Dq * Dq + idx] = __float2half_rn(W[k * Dq + n]);
}

// ---------------- positional-embedding add, enc+dec fused ----------------
__global__ void __launch_bounds__(256) add_pos2_kernel(const float* __restrict__ x0,
                                                       const float* __restrict__ x1,
                                                       float* __restrict__ out0,
                                                       float* __restrict__ out1,
                                                       __half* __restrict__ o0,
                                                       __half* __restrict__ o1) {
    int idx = blockIdx.x * 256 + threadIdx.x;
    const float* x = blockIdx.y ? x1 : x0;
    float* out     = blockIdx.y ? out1 : out0;
    __half* o16    = blockIdx.y ? o1 : o0;
    int d = idx & (Dq - 1);
    int s = (idx >> 9) & (Sq - 1);
    float freq  = expf((float)d * -0.0359778920794f);
    float angle = (float)s * freq;
    float pe = (d & 1) ? cosf(angle) : sinf(angle);
    float r = x[idx] + pe;
    out[idx] = r;
    o16[idx] = __float2half_rn(r);
}

// ---------------- fused LayerNorm + residual, enc+dec fused ----------------
__global__ void __launch_bounds__(256) ln_add2_kernel(
    const float* __restrict__ xe, const float* __restrict__ xd,
    const float* __restrict__ ge, const float* __restrict__ be,
    const float* __restrict__ gd, const float* __restrict__ bd,
    const float* __restrict__ basee, const float* __restrict__ based,
    float* __restrict__ outd, __half* __restrict__ o16e) {
    __shared__ float red[256];
    int t = threadIdx.x;
    int z = blockIdx.y;
    size_t off = (size_t)blockIdx.x * Dq;
    const float* x     = z ? xd : xe;
    const float* gamma = z ? gd : ge;
    const float* beta  = z ? bd : be;
    const float* basep = z ? based : basee;
    float scale        = z ? 2.0f : 1.0f;

    float v0 = x[off + t];
    float v1 = x[off + t + 256];

    red[t] = v0 + v1;
    __syncthreads();
    #pragma unroll
    for (int s2 = 128; s2 > 0; s2 >>= 1) {
        if (t < s2) red[t] += red[t + s2];
        __syncthreads();
    }
    float mu = red[0] * (1.0f / 512.0f);
    __syncthreads();

    float d0 = v0 - mu, d1 = v1 - mu;
    red[t] = d0 * d0 + d1 * d1;
    __syncthreads();
    #pragma unroll
    for (int s2 = 128; s2 > 0; s2 >>= 1) {
        if (t < s2) red[t] += red[t + s2];
        __syncthreads();
    }
    float var = red[0] * (1.0f / 512.0f);
    float rs  = rsqrtf(var + 1e-3f);

    float r0 = basep[off + t]       + scale * (d0 * rs * gamma[t]       + beta[t]);
    float r1 = basep[off + t + 256] + scale * (d1 * rs * gamma[t + 256] + beta[t + 256]);
    if (z) {
        outd[off + t]       = r0;
        outd[off + t + 256] = r1;
    } else {
        o16e[off + t]       = __float2half_rn(r0);
        o16e[off + t + 256] = __float2half_rn(r1);
    }
}

// ---------------- GEMM core: 128x128 tile, fp16, K32 cp.async double-buffered ----------------
// per buffer: sA 128x40 fp16 = 10240 B, sB 128x40 fp16 = 10240 B -> 20480 B; two buffers
#define KAPAD 40
#define GBUF  20480
#define GB_B  10240
#define GEMM_SMEM (2 * GBUF)   // 40960 -> 2 CTAs/SM

struct GemmFrag { float acc[2][8][4]; };

__device__ __forceinline__ void gemm_core(uint32_t sb,
                                          const __half* __restrict__ A16,
                                          const __half* __restrict__ B16,
                                          int m0, int n0, GemmFrag& F) {
    int tid = threadIdx.x;
    int wid = tid >> 5, lane = tid & 31;
    int wm = (wid & 3) * 32;
    int wn = (wid >> 2) * 64;

    #pragma unroll
    for (int i = 0; i < 2; i++)
        #pragma unroll
        for (int j = 0; j < 8; j++)
            #pragma unroll
            for (int q = 0; q < 4; q++) F.acc[i][j][q] = 0.0f;

    int la = lane & 15;
    int lacol = (lane >> 4) << 3;
    int nrow = (lane & 7) + ((lane >> 4) << 3);
    int koff = ((lane >> 3) & 1) << 3;

    int rT = tid >> 1, cT = (tid & 1) * 16;   // 128 rows, 2 thr/row, 16 elems (2x CPA16)

    auto prefetch = [&](int kc, uint32_t bofs) {
        int kofs = kc * 32;
        const __half* pA = &A16[(size_t)(m0 + rT) * Dq + kofs + cT];
        const __half* pB = &B16[(size_t)(n0 + rT) * Dq + kofs + cT];
        uint32_t so = sb + bofs + (uint32_t)((rT * KAPAD + cT) * 2);
        CPA16(so, pA);
        CPA16(so + 16, pA + 8);
        CPA16(so + GB_B, pB);
        CPA16(so + GB_B + 16, pB + 8);
    };

    prefetch(0, 0);
    CP_COMMIT();
    CP_WAIT0();
    __syncthreads();

    for (int kc = 0; kc < 16; kc++) {
        uint32_t cur = (kc & 1) ? GBUF : 0;
        if (kc < 15) {
            prefetch(kc + 1, (kc & 1) ? 0 : GBUF);
            CP_COMMIT();
        }

        #pragma unroll
        for (int ks = 0; ks < 2; ks++) {
            int kk = ks * 16;
            uint32_t a[2][4];
            #pragma unroll
            for (int ma = 0; ma < 2; ma++) {
                int row = wm + ma * 16 + la;
                ldsm_x4(a[ma], sb + cur + (uint32_t)((row * KAPAD + kk + lacol) * 2));
            }
            uint32_t bq[4][4];
            #pragma unroll
            for (int nb = 0; nb < 4; nb++) {
                int rown = wn + nb * 16 + nrow;
                ldsm_x4(bq[nb], sb + cur + GB_B + (uint32_t)((rown * KAPAD + kk + koff) * 2));
            }
            #pragma unroll
            for (int ma = 0; ma < 2; ma++)
                #pragma unroll
                for (int nb = 0; nb < 4; nb++) {
                    mma16816h(F.acc[ma][2 * nb],     a[ma], &bq[nb][0]);
                    mma16816h(F.acc[ma][2 * nb + 1], a[ma], &bq[nb][2]);
                }
        }

        if (kc < 15) CP_WAIT0();
        __syncthreads();
    }
}

// ---- generic GEMM: fp32 out (+addend) and/or fp16 out (+scaled fp16 copy) ----
__global__ void __launch_bounds__(256) gemm_mma_kernel(
    const __half* __restrict__ A16, const __half* __restrict__ B16,
    const float* __restrict__ addend, float* __restrict__ C,
    __half* __restrict__ C16, __half* __restrict__ C16s) {
    extern __shared__ char smem[];
    uint32_t sb = smem_u32(smem);
    int m0 = blockIdx.y * 128, n0 = blockIdx.x * 128;
    GemmFrag F;
    gemm_core(sb, A16, B16, m0, n0, F);

    int wid = threadIdx.x >> 5, lane = threadIdx.x & 31;
    int wm = (wid & 3) * 32, wn = (wid >> 2) * 64;
    int g = lane >> 2, tq = lane & 3;
    #pragma unroll
    for (int ma = 0; ma < 2; ma++) {
        int row = m0 + wm + ma * 16 + g;
        #pragma unroll
        for (int na = 0; na < 8; na++) {
            int col = n0 + wn + na * 8 + tq * 2;
            size_t o0 = (size_t)row * Dq + col;
            size_t o1 = o0 + 8 * Dq;
            float2 r0 = make_float2(F.acc[ma][na][0], F.acc[ma][na][1]);
            float2 r1 = make_float2(F.acc[ma][na][2], F.acc[ma][na][3]);
            if (addend) {
                float2 a0 = *(const float2*)&addend[o0];
                float2 a1 = *(const float2*)&addend[o1];
                r0.x += a0.x; r0.y += a0.y;
                r1.x += a1.x; r1.y += a1.y;
            }
            if (C) {
                *(float2*)&C[o0] = r0;
                *(float2*)&C[o1] = r1;
            }
            if (C16) {
                *(uint32_t*)&C16[o0] = pkh2(r0.x, r0.y);
                *(uint32_t*)&C16[o1] = pkh2(r1.x, r1.y);
            }
            if (C16s) {
                *(uint32_t*)&C16s[o0] = pkh2(r0.x * LOG2E_DIV_H, r0.y * LOG2E_DIV_H);
                *(uint32_t*)&C16s[o1] = pkh2(r1.x * LOG2E_DIV_H, r1.y * LOG2E_DIV_H);
            }
        }
    }
}

// ---- fused QKV GEMM for BOTH enc and dec (6 weights); Q outputs pre-scaled ----
__global__ void __launch_bounds__(256) gemm_qkv6_kernel(
    const __half* __restrict__ Ae, const __half* __restrict__ Ad,
    const __half* __restrict__ W16,
    __half* __restrict__ Qe, __half* __restrict__ Ke, __half* __restrict__ Ve,
    __half* __restrict__ Qd, __half* __restrict__ Kd, __half* __restrict__ Vd) {
    extern __shared__ char smem[];
    uint32_t sb = smem_u32(smem);
    int w = blockIdx.x >> 2;                 // 0..5: encQ,encK,encV,decQ,decK,decV
    int n0 = (blockIdx.x & 3) * 128;
    int m0 = blockIdx.y * 128;
    const __half* A16 = (w < 3) ? Ae : Ad;
    int widx = (w < 3) ? w : (w + 1);
    const __half* B16 = W16 + (size_t)widx * Dq * Dq;
    __half* O16 = (w == 0) ? Qe : (w == 1) ? Ke : (w == 2) ? Ve :
                  (w == 3) ? Qd : (w == 4) ? Kd : Vd;
    float sc = (w == 0 || w == 3) ? LOG2E_DIV_H : 1.0f;

    GemmFrag F;
    gemm_core(sb, A16, B16, m0, n0, F);

    int wid = threadIdx.x >> 5, lane = threadIdx.x & 31;
    int wm = (wid & 3) * 32, wn = (wid >> 2) * 64;
    int g = lane >> 2, tq = lane & 3;
    #pragma unroll
    for (int ma = 0; ma < 2; ma++) {
        int row = m0 + wm + ma * 16 + g;
        #pragma unroll
        for (int na = 0; na < 8; na++) {
            int col = n0 + wn + na * 8 + tq * 2;
            size_t o0 = (size_t)row * Dq + col;
            size_t o1 = o0 + 8 * Dq;
            *(uint32_t*)&O16[o0] = pkh2(F.acc[ma][na][0] * sc, F.acc[ma][na][1] * sc);
            *(uint32_t*)&O16[o1] = pkh2(F.acc[ma][na][2] * sc, F.acc[ma][na][3] * sc);
        }
    }
}

// ---------------- flash attention: enc+dec fused (R15, proven) ----------------
#define FP 72
#define FQ16 0
#define FKV  18432
#define KK16 0
#define VV16 9216
#define KVBUF 18432
#define FLASH_SMEM (FKV + 2 * KVBUF)   // 55296 -> 2 CTAs/SM

__global__ void __launch_bounds__(256) flash2_mma_kernel(
    const __half* __restrict__ Qe, const __half* __restrict__ Ke, const __half* __restrict__ Ve,
    const __half* __restrict__ Qd, const __half* __restrict__ Kd, const __half* __restrict__ Vd,
    float* __restrict__ Oe, float* __restrict__ Od) {
    extern __shared__ char smem[];
    uint32_t sb = smem_u32(smem);

    int tid = threadIdx.x, wid = tid >> 5, lane = tid & 31;
    int wm = wid * 16;
    int g = lane >> 2, tq = lane & 3;
    int qb = blockIdx.x, h = blockIdx.y;
    int bz = blockIdx.z;
    int isd = bz >> 3;
    int b = bz & 7;
    const __half* Q16 = isd ? Qd : Qe;
    const __half* K16 = isd ? Kd : Ke;
    const __half* V16 = isd ? Vd : Ve;
    float* O = isd ? Od : Oe;
    size_t baseQ  = ((size_t)b * Sq + (size_t)qb * 128) * Dq + h * DHq;
    size_t baseKV = (size_t)b * Sq * Dq + h * DHq;

    int rQ = tid >> 1, cQ = (tid & 1) * 32;
    int rK = tid >> 2, cK = (tid & 3) * 16;

    auto kvload = [&](int kb, uint32_t bofs) {
        size_t go = baseKV + (size_t)(kb * 64 + rK) * Dq + cK;
        uint32_t so = sb + FKV + bofs + (uint32_t)((rK * FP + cK) * 2);
        #pragma unroll
        for (int q = 0; q < 2; q++) {
            CPA16(so + KK16 + q * 16, &K16[go + q * 8]);
            CPA16(so + VV16 + q * 16, &V16[go + q * 8]);
        }
    };

    {
        size_t go = baseQ + (size_t)rQ * Dq + cQ;
        uint32_t so = sb + FQ16 + (uint32_t)((rQ * FP + cQ) * 2);
        #pragma unroll
        for (int q = 0; q < 4; q++)
            CPA16(so + q * 16, &Q16[go + q * 8]);
        kvload(0, 0);
        CP_COMMIT();
        CP_WAIT0();
        __syncthreads();
    }

    float oacc[8][4];
    #pragma unroll
    for (int j = 0; j < 8; j++)
        #pragma unroll
        for (int q = 0; q < 4; q++) oacc[j][q] = 0.0f;
    float mr0 = -1e30f, mr1 = -1e30f, lr0 = 0.0f, lr1 = 0.0f;

    uint32_t aQ = (uint32_t)(((wm + (lane & 15)) * FP + ((lane >> 4) << 3)) * 2);
    int nrow = (lane & 7) + ((lane >> 4) << 3);
    int koff = ((lane >> 3) & 1) << 3;
    uint32_t bKp = (uint32_t)((nrow * FP + koff) * 2);
    uint32_t bVp = (uint32_t)(((lane & 15) * FP + ((lane >> 4) << 3)) * 2);

    for (int kb = 0; kb < 16; kb++) {
        uint32_t cur = FKV + ((kb & 1) ? KVBUF : 0);
        if (kb < 15) {
            kvload(kb + 1, (kb & 1) ? 0 : KVBUF);
            CP_COMMIT();
        }

        float sacc[8][4];
        #pragma unroll
        for (int j = 0; j < 8; j++)
            #pragma unroll
            for (int q = 0; q < 4; q++) sacc[j][q] = 0.0f;

        #pragma unroll
        for (int ks = 0; ks < 4; ks++) {
            uint32_t aq[4];
            ldsm_x4(aq, sb + FQ16 + aQ + ks * 32);
            #pragma unroll
            for (int nb = 0; nb < 4; nb++) {
                uint32_t bk[4];
                uint32_t off = cur + KK16 + bKp + (uint32_t)(nb * 16 * FP * 2) + ks * 32;
                ldsm_x4(bk, sb + off);
                mma16816h(sacc[2 * nb],     aq, &bk[0]);
                mma16816h(sacc[2 * nb + 1], aq, &bk[2]);
            }
        }

        float rmax0 = -1e30f, rmax1 = -1e30f;
        #pragma unroll
        for (int j = 0; j < 8; j++) {
            rmax0 = fmaxf(rmax0, fmaxf(sacc[j][0], sacc[j][1]));
            rmax1 = fmaxf(rmax1, fmaxf(sacc[j][2], sacc[j][3]));
        }
        rmax0 = fmaxf(rmax0, __shfl_xor_sync(0xffffffffu, rmax0, 1));
        rmax0 = fmaxf(rmax0, __shfl_xor_sync(0xffffffffu, rmax0, 2));
        rmax1 = fmaxf(rmax1, __shfl_xor_sync(0xffffffffu, rmax1, 1));
        rmax1 = fmaxf(rmax1, __shfl_xor_sync(0xffffffffu, rmax1, 2));
        float mn0 = fmaxf(mr0, rmax0), mn1 = fmaxf(mr1, rmax1);
        float al0 = exp2f(mr0 - mn0), al1 = exp2f(mr1 - mn1);
        float sum0 = 0.0f, sum1 = 0.0f;
        #pragma unroll
        for (int j = 0; j < 8; j++) {
            sacc[j][0] = exp2f(sacc[j][0] - mn0);
            sacc[j][1] = exp2f(sacc[j][1] - mn0);
            sacc[j][2] = exp2f(sacc[j][2] - mn1);
            sacc[j][3] = exp2f(sacc[j][3] - mn1);
            sum0 += sacc[j][0] + sacc[j][1];
            sum1 += sacc[j][2] + sacc[j][3];
        }
        sum0 += __shfl_xor_sync(0xffffffffu, sum0, 1);
        sum0 += __shfl_xor_sync(0xffffffffu, sum0, 2);
        sum1 += __shfl_xor_sync(0xffffffffu, sum1, 1);
        sum1 += __shfl_xor_sync(0xffffffffu, sum1, 2);
        lr0 = lr0 * al0 + sum0; mr0 = mn0;
        lr1 = lr1 * al1 + sum1; mr1 = mn1;

        #pragma unroll
        for (int j = 0; j < 8; j++) {
            oacc[j][0] *= al0; oacc[j][1] *= al0;
            oacc[j][2] *= al1; oacc[j][3] *= al1;
        }

        uint32_t ph[4][4];
        #pragma unroll
        for (int k2 = 0; k2 < 4; k2++) {
            ph[k2][0] = pkh2(sacc[2*k2][0],   sacc[2*k2][1]);
            ph[k2][1] = pkh2(sacc[2*k2][2],   sacc[2*k2][3]);
            ph[k2][2] = pkh2(sacc[2*k2+1][0], sacc[2*k2+1][1]);
            ph[k2][3] = pkh2(sacc[2*k2+1][2], sacc[2*k2+1][3]);
        }

        #pragma unroll
        for (int k2 = 0; k2 < 4; k2++) {
            #pragma unroll
            for (int nb = 0; nb < 4; nb++) {
                uint32_t bv[4];
                uint32_t off = cur + VV16 + bVp + (uint32_t)((k2 * 16 * FP + nb * 16) * 2);
                ldsm_x4t(bv, sb + off);
                mma16816h(oacc[2 * nb],     ph[k2], &bv[0]);
                mma16816h(oacc[2 * nb + 1], ph[k2], &bv[2]);
            }
        }

        if (kb < 15) CP_WAIT0();
        __syncthreads();
    }

    float il0 = 1.0f / lr0, il1 = 1.0f / lr1;
    int row0 = wm + g, row1 = wm + g + 8;
    #pragma unroll
    for (int na = 0; na < 8; na++) {
        int col = na * 8 + tq * 2;
        size_t o0 = baseQ + (size_t)row0 * Dq + col;
        size_t o1 = baseQ + (size_t)row1 * Dq + col;
        *(float2*)&O[o0] = make_float2(oacc[na][0] * il0, oacc[na][1] * il0);
        *(float2*)&O[o1] = make_float2(oacc[na][2] * il1, oacc[na][3] * il1);
    }
}

// ---- single flash for eda (fp16 out) ----
__global__ void __launch_bounds__(256) flash_mma_kernel(
    const __half* __restrict__ Q16,
    const __half* __restrict__ K16,
    const __half* __restrict__ V16,
    __half* __restrict__ O16) {
    extern __shared__ char smem[];
    uint32_t sb = smem_u32(smem);

    int tid = threadIdx.x, wid = tid >> 5, lane = tid & 31;
    int wm = wid * 16;
    int g = lane >> 2, tq = lane & 3;
    int qb = blockIdx.x, h = blockIdx.y, b = blockIdx.z;
    size_t baseQ  = ((size_t)b * Sq + (size_t)qb * 128) * Dq + h * DHq;
    size_t baseKV = (size_t)b * Sq * Dq + h * DHq;

    int rQ = tid >> 1, cQ = (tid & 1) * 32;
    int rK = tid >> 2, cK = (tid & 3) * 16;

    auto kvload = [&](int kb, uint32_t bofs) {
        size_t go = baseKV + (size_t)(kb * 64 + rK) * Dq + cK;
        uint32_t so = sb + FKV + bofs + (uint32_t)((rK * FP + cK) * 2);
        #pragma unroll
        for (int q = 0; q < 2; q++) {
            CPA16(so + KK16 + q * 16, &K16[go + q * 8]);
            CPA16(so + VV16 + q * 16, &V16[go + q * 8]);
        }
    };

    {
        size_t go = baseQ + (size_t)rQ * Dq + cQ;
        uint32_t so = sb + FQ16 + (uint32_t)((rQ * FP + cQ) * 2);
        #pragma unroll
        for (int q = 0; q < 4; q++)
            CPA16(so + q * 16, &Q16[go + q * 8]);
        kvload(0, 0);
        CP_COMMIT();
        CP_WAIT0();
        __syncthreads();
    }

    float oacc[8][4];
    #pragma unroll
    for (int j = 0; j < 8; j++)
        #pragma unroll
        for (int q = 0; q < 4; q++) oacc[j][q] = 0.0f;
    float mr0 = -1e30f, mr1 = -1e30f, lr0 = 0.0f, lr1 = 0.0f;

    uint32_t aQ = (uint32_t)(((wm + (lane & 15)) * FP + ((lane >> 4) << 3)) * 2);
    int nrow = (lane & 7) + ((lane >> 4) << 3);
    int koff = ((lane >> 3) & 1) << 3;
    uint32_t bKp = (uint32_t)((nrow * FP + koff) * 2);
    uint32_t bVp = (uint32_t)(((lane & 15) * FP + ((lane >> 4) << 3)) * 2);

    for (int kb = 0; kb < 16; kb++) {
        uint32_t cur = FKV + ((kb & 1) ? KVBUF : 0);
        if (kb < 15) {
            kvload(kb + 1, (kb & 1) ? 0 : KVBUF);
            CP_COMMIT();
        }

        float sacc[8][4];
        #pragma unroll
        for (int j = 0; j < 8; j++)
            #pragma unroll
            for (int q = 0; q < 4; q++) sacc[j][q] = 0.0f;

        #pragma unroll
        for (int ks = 0; ks < 4; ks++) {
            uint32_t aq[4];
            ldsm_x4(aq, sb + FQ16 + aQ + ks * 32);
            #pragma unroll
            for (int nb = 0; nb < 4; nb++) {
                uint32_t bk[4];
                uint32_t off = cur + KK16 + bKp + (uint32_t)(nb * 16 * FP * 2) + ks * 32;
                ldsm_x4(bk, sb + off);
                mma16816h(sacc[2 * nb],     aq, &bk[0]);
                mma16816h(sacc[2 * nb + 1], aq, &bk[2]);
            }
        }

        float rmax0 = -1e30f, rmax1 = -1e30f;
        #pragma unroll
        for (int j = 0; j < 8; j++) {
            rmax0 = fmaxf(rmax0, fmaxf(sacc[j][0], sacc[j][1]));
            rmax1 = fmaxf(rmax1, fmaxf(sacc[j][2], sacc[j][3]));
        }
        rmax0 = fmaxf(rmax0, __shfl_xor_sync(0xffffffffu, rmax0, 1));
        rmax0 = fmaxf(rmax0, __shfl_xor_sync(0xffffffffu, rmax0, 2));
        rmax1 = fmaxf(rmax1, __shfl_xor_sync(0xffffffffu, rmax1, 1));
        rmax1 = fmaxf(rmax1, __shfl_xor_sync(0xffffffffu, rmax1, 2));
        float mn0 = fmaxf(mr0, rmax0), mn1 = fmaxf(mr1, rmax1);
        float al0 = exp2f(mr0 - mn0), al1 = exp2f(mr1 - mn1);
        float sum0 = 0.0f, sum1 = 0.0f;
        #pragma unroll
        for (int j = 0; j < 8; j++) {
            sacc[j][0] = exp2f(sacc[j][0] - mn0);
            sacc[j][1] = exp2f(sacc[j][1] - mn0);
            sacc[j][2] = exp2f(sacc[j][2] - mn1);
            sacc[j][3] = exp2f(sacc[j][3] - mn1);
            sum0 += sacc[j][0] + sacc[j][1];
            sum1 += sacc[j][2] + sacc[j][3];
        }
        sum0 += __shfl_xor_sync(0xffffffffu, sum0, 1);
        sum0 += __shfl_xor_sync(0xffffffffu, sum0, 2);
        sum1 += __shfl_xor_sync(0xffffffffu, sum1, 1);
        sum1 += __shfl_xor_sync(0xffffffffu, sum1, 2);
        lr0 = lr0 * al0 + sum0; mr0 = mn0;
        lr1 = lr1 * al1 + sum1; mr1 = mn1;

        #pragma unroll
        for (int j = 0; j < 8; j++) {
            oacc[j][0] *= al0; oacc[j][1] *= al0;
            oacc[j][2] *= al1; oacc[j][3] *= al1;
        }

        uint32_t ph[4][4];
        #pragma unroll
        for (int k2 = 0; k2 < 4; k2++) {
            ph[k2][0] = pkh2(sacc[2*k2][0],   sacc[2*k2][1]);
            ph[k2][1] = pkh2(sacc[2*k2][2],   sacc[2*k2][3]);
            ph[k2][2] = pkh2(sacc[2*k2+1][0], sacc[2*k2+1][1]);
            ph[k2][3] = pkh2(sacc[2*k2+1][2], sacc[2*k2+1][3]);
        }

        #pragma unroll
        for (int k2 = 0; k2 < 4; k2++) {
            #pragma unroll
            for (int nb = 0; nb < 4; nb++) {
                uint32_t bv[4];
                uint32_t off = cur + VV16 + bVp + (uint32_t)((k2 * 16 * FP + nb * 16) * 2);
                ldsm_x4t(bv, sb + off);
                mma16816h(oacc[2 * nb],     ph[k2], &bv[0]);
                mma16816h(oacc[2 * nb + 1], ph[k2], &bv[2]);
            }
        }

        if (kb < 15) CP_WAIT0();
        __syncthreads();
    }

    float il0 = 1.0f / lr0, il1 = 1.0f / lr1;
    int row0 = wm + g, row1 = wm + g + 8;
    #pragma unroll
    for (int na = 0; na < 8; na++) {
        int col = na * 8 + tq * 2;
        size_t o0 = baseQ + (size_t)row0 * Dq + col;
        size_t o1 = baseQ + (size_t)row1 * Dq + col;
        *(uint32_t*)&O16[o0] = pkh2(oacc[na][0] * il0, oacc[na][1] * il0);
        *(uint32_t*)&O16[o1] = pkh2(oacc[na][2] * il1, oacc[na][3] * il1);
    }
}

// ---------------- launcher ----------------
extern "C" void kernel_launch(void* const* d_in, const int* in_sizes, int n_in,
                              void* d_out, int out_size) {
    const float* in0 = (const float*)d_in[0];
    const float* in1 = (const float*)d_in[1];
    const float* ge = (const float*)d_in[6];
    const float* be = (const float*)d_in[7];
    const float* gd = (const float*)d_in[12];
    const float* bd = (const float*)d_in[13];
    float* out = (float*)d_out;

    float *E, *DI, *Se, *Sd, *I;
    __half *Ae, *Ad, *Qe, *Ke, *Ve, *Qd, *Kd, *Vd, *EO16, *EOq16, *EDA16, *W16;
    cudaGetSymbolAddress((void**)&E,     g_E);
    cudaGetSymbolAddress((void**)&DI,    g_DI);
    cudaGetSymbolAddress((void**)&Se,    g_Se);
    cudaGetSymbolAddress((void**)&Sd,    g_Sd);
    cudaGetSymbolAddress((void**)&I,     g_I);
    cudaGetSymbolAddress((void**)&Ae,    g_Ae16);
    cudaGetSymbolAddress((void**)&Ad,    g_Ad16);
    cudaGetSymbolAddress((void**)&Qe,    g_Qe16);
    cudaGetSymbolAddress((void**)&Ke,    g_Ke16);
    cudaGetSymbolAddress((void**)&Ve,    g_Ve16);
    cudaGetSymbolAddress((void**)&Qd,    g_Qd16);
    cudaGetSymbolAddress((void**)&Kd,    g_Kd16);
    cudaGetSymbolAddress((void**)&Vd,    g_Vd16);
    cudaGetSymbolAddress((void**)&EO16,  g_EO16);
    cudaGetSymbolAddress((void**)&EOq16, g_EOq16);
    cudaGetSymbolAddress((void**)&EDA16, g_EDA16);
    cudaGetSymbolAddress((void**)&W16,   g_W16);

    cudaFuncSetAttribute(gemm_mma_kernel,   cudaFuncAttributeMaxDynamicSharedMemorySize, GEMM_SMEM);
    cudaFuncSetAttribute(gemm_qkv6_kernel,  cudaFuncAttributeMaxDynamicSharedMemorySize, GEMM_SMEM);
    cudaFuncSetAttribute(flash2_mma_kernel, cudaFuncAttributeMaxDynamicSharedMemorySize, FLASH_SMEM);
    cudaFuncSetAttribute(flash_mma_kernel,  cudaFuncAttributeMaxDynamicSharedMemorySize, FLASH_SMEM);

    dim3 ggrid(Dq / 128, BSr / 128);        // (4, 64)
    dim3 qkv6grid(6 * Dq / 128, BSr / 128); // (24, 64)
    dim3 f2grid(Sq / 128, Hq, 2 * Bq);      // (8, 8, 16)
    dim3 fgrid(Sq / 128, Hq, Bq);           // (8, 8, 8)
    const int WSZ = Dq * Dq;

    dim3 wgrid(WSZ / 256, 8);
    cvt_wt_all_kernel<<<wgrid, 256>>>(
        (const float*)d_in[2], (const float*)d_in[3], (const float*)d_in[4],
        (const float*)d_in[5], (const float*)d_in[8], (const float*)d_in[9],
        (const float*)d_in[10], (const float*)d_in[11], W16);

    dim3 pgrid(BSD / 256, 2);
    add_pos2_kernel<<<pgrid, 256>>>(in0, in1, E, DI, Ae, Ad);

    gemm_qkv6_kernel<<<qkv6grid, 256, GEMM_SMEM>>>(Ae, Ad, W16, Qe, Ke, Ve, Qd, Kd, Vd);

    flash2_mma_kernel<<<f2grid, 256, FLASH_SMEM>>>(Qe, Ke, Ve, Qd, Kd, Vd, Se, Sd);

    dim3 lgrid(BSr, 2);
    ln_add2_kernel<<<lgrid, 256>>>(Se, Sd, ge, be, gd, bd, E, DI, I, Ae);

    gemm_mma_kernel<<<ggrid, 256, GEMM_SMEM>>>(Ae, W16 + 3 * WSZ, E, nullptr, EO16, EOq16);

    flash_mma_kernel<<<fgrid, 256, FLASH_SMEM>>>(EOq16, EO16, EO16, EDA16);

    gemm_mma_kernel<<<ggrid, 256, GEMM_SMEM>>>(EDA16, W16 + 7 * WSZ, I, out, nullptr, nullptr);
}